// round 4
// baseline (speedup 1.0000x reference)
#include <cuda_runtime.h>

// Problem constants (fixed by the dataset generator).
#define NN   40000
#define EE   640000
#define FIN  128
#define FHID 512
#define FOUT 256

// ---------------- scratch (static device globals; no allocation allowed) ----
__device__ int   g_is64;
__device__ int   g_src[EE];
__device__ int   g_dst[EE];
__device__ int   g_cnt[NN];
__device__ int   g_rowptr[NN + 1];
__device__ int   g_cursor[NN];
__device__ int   g_col[EE];
__device__ float g_aggA[(size_t)NN * FIN];   // mean-aggregated x        (20 MB)
__device__ float g_h   [(size_t)NN * FHID];  // layer-1 output           (82 MB)
__device__ float g_p   [(size_t)NN * FOUT];  // h @ W2l                  (40 MB)
__device__ float g_agg2[(size_t)NN * FOUT];  // mean-aggregated p        (40 MB)

// ---------------- edge dtype detection + conversion ---------------------------
// If edge_index is int64 (little-endian, values < 40000), every odd int32 word
// of the first 64 entries is 0. If it is int32, those words are random node ids.
__global__ void detect_kernel(const int* __restrict__ ei32) {
    if (threadIdx.x == 0 && blockIdx.x == 0) {
        int all0 = 1;
        for (int i = 0; i < 64; i++)
            if (ei32[2 * i + 1] != 0) all0 = 0;
        g_is64 = all0;
    }
}

__global__ void convert_kernel(const int* __restrict__ ei32) {
    int e = blockIdx.x * blockDim.x + threadIdx.x;
    if (e >= EE) return;
    int is64 = g_is64;
    int s, d;
    if (is64) {
        const long long* ei64 = (const long long*)ei32;
        s = (int)ei64[e];
        d = (int)ei64[EE + e];
    } else {
        s = ei32[e];
        d = ei32[EE + e];
    }
    g_src[e] = s;
    g_dst[e] = d;
}

// ---------------- CSR build --------------------------------------------------
__global__ void zero_cnt_kernel() {
    int i = blockIdx.x * blockDim.x + threadIdx.x;
    if (i < NN) g_cnt[i] = 0;
}

__global__ void hist_kernel() {
    int e = blockIdx.x * blockDim.x + threadIdx.x;
    if (e < EE) atomicAdd(&g_cnt[g_dst[e]], 1);
}

// One-block exclusive scan: each thread owns a contiguous chunk, serial-sums it,
// block-scans the 1024 partials, then writes running prefixes back.
__global__ void scan_kernel() {
    const int T = 1024;
    const int CH = (NN + T - 1) / T;  // 40
    __shared__ int s[T];
    int t = threadIdx.x;
    int base = t * CH;

    int sum = 0;
    for (int j = 0; j < CH; j++) {
        int i = base + j;
        if (i < NN) sum += g_cnt[i];
    }
    s[t] = sum;
    __syncthreads();
    for (int off = 1; off < T; off <<= 1) {
        int v = (t >= off) ? s[t - off] : 0;
        __syncthreads();
        s[t] += v;
        __syncthreads();
    }
    int run = s[t] - sum;  // exclusive prefix for this thread's chunk
    for (int j = 0; j < CH; j++) {
        int i = base + j;
        if (i < NN) {
            g_rowptr[i] = run;
            g_cursor[i] = run;
            run += g_cnt[i];
        }
    }
    if (t == 0) g_rowptr[NN] = EE;
}

__global__ void fill_kernel() {
    int e = blockIdx.x * blockDim.x + threadIdx.x;
    if (e < EE) {
        int d   = g_dst[e];
        int pos = atomicAdd(&g_cursor[d], 1);
        g_col[pos] = g_src[e];
    }
}

// ---------------- mean aggregation over CSR ----------------------------------
// One warp per node. Lane l owns float4 chunk(s) of the feature row.
// VPL = float4 chunks per lane (1 -> F=128, 2 -> F=256).
template <int VPL>
__global__ void agg_kernel(const float* __restrict__ feat,
                           float* __restrict__ out) {
    int node = blockIdx.x * (blockDim.x >> 5) + (threadIdx.x >> 5);
    if (node >= NN) return;
    int lane = threadIdx.x & 31;
    int beg = g_rowptr[node];
    int end = g_rowptr[node + 1];

    const int F = VPL * 128;
    float4 acc[VPL];
#pragma unroll
    for (int v = 0; v < VPL; v++) acc[v] = make_float4(0.f, 0.f, 0.f, 0.f);

    for (int j = beg; j < end; j++) {
        int sidx = __ldg(&g_col[j]);
        const float4* row = (const float4*)(feat + (size_t)sidx * F);
#pragma unroll
        for (int v = 0; v < VPL; v++) {
            float4 r = row[lane + v * 32];
            acc[v].x += r.x; acc[v].y += r.y; acc[v].z += r.z; acc[v].w += r.w;
        }
    }
    float inv = 1.0f / (float)max(end - beg, 1);
    float4* o = (float4*)(out + (size_t)node * F);
#pragma unroll
    for (int v = 0; v < VPL; v++) {
        acc[v].x *= inv; acc[v].y *= inv; acc[v].z *= inv; acc[v].w *= inv;
        o[lane + v * 32] = acc[v];
    }
}

// ---------------- fp32 SIMT GEMM ----------------------------------------------
// C[M,N] = A1[M,K] @ B1[K,N]  (+ A2[M,K] @ B2[K,N])  (+ bias[N]) (+ D[M,N]) (relu?)
// Row-major everywhere. BM=128, BN=64, BK=16, 256 threads, 8x4 micro-tile.
__global__ void __launch_bounds__(256)
gemm_kernel(const float* __restrict__ A1, const float* __restrict__ B1,
            const float* __restrict__ A2, const float* __restrict__ B2,
            const float* __restrict__ bias, const float* __restrict__ D,
            float* __restrict__ C, int M, int N, int K, int relu) {
    const int BM = 128, BN = 64, BK = 16;
    __shared__ __align__(16) float As[BK][BM];  // transposed A tile
    __shared__ __align__(16) float Bs[BK][BN];

    int tid = threadIdx.x;
    int m0 = blockIdx.y * BM;
    int n0 = blockIdx.x * BN;
    int ty = tid >> 4;   // 0..15 -> m offset ty*8
    int tx = tid & 15;   // 0..15 -> n offset tx*4

    float acc[8][4];
#pragma unroll
    for (int i = 0; i < 8; i++)
#pragma unroll
        for (int j = 0; j < 4; j++) acc[i][j] = 0.f;

    for (int ph = 0; ph < 2; ph++) {
        const float* A = ph ? A2 : A1;
        const float* B = ph ? B2 : B1;
        if (A == nullptr) break;

        int ktiles = K / BK;
        // register-prefetch software pipeline
        float4 pa[2];
        float4 pb;
        {
#pragma unroll
            for (int u = 0; u < 2; u++) {
                int f = tid + u * 256;          // float4 id in [0,512)
                int r = f >> 2, kc = f & 3;
                int gm = m0 + r;
                pa[u] = (gm < M) ? *(const float4*)(A + (size_t)gm * K + kc * 4)
                                 : make_float4(0.f, 0.f, 0.f, 0.f);
            }
            int r = tid >> 4, nc = tid & 15;
            pb = *(const float4*)(B + (size_t)r * N + n0 + nc * 4);
        }

        for (int kt = 0; kt < ktiles; kt++) {
            // commit prefetched tile to smem
#pragma unroll
            for (int u = 0; u < 2; u++) {
                int f = tid + u * 256;
                int r = f >> 2, kc = f & 3;
                As[kc * 4 + 0][r] = pa[u].x;
                As[kc * 4 + 1][r] = pa[u].y;
                As[kc * 4 + 2][r] = pa[u].z;
                As[kc * 4 + 3][r] = pa[u].w;
            }
            {
                int r = tid >> 4, nc = tid & 15;
                *(float4*)&Bs[r][nc * 4] = pb;
            }
            __syncthreads();

            // prefetch next tile
            if (kt + 1 < ktiles) {
                int k0n = (kt + 1) * BK;
#pragma unroll
                for (int u = 0; u < 2; u++) {
                    int f = tid + u * 256;
                    int r = f >> 2, kc = f & 3;
                    int gm = m0 + r;
                    pa[u] = (gm < M)
                                ? *(const float4*)(A + (size_t)gm * K + k0n + kc * 4)
                                : make_float4(0.f, 0.f, 0.f, 0.f);
                }
                int r = tid >> 4, nc = tid & 15;
                pb = *(const float4*)(B + (size_t)(k0n + r) * N + n0 + nc * 4);
            }

#pragma unroll
            for (int kk = 0; kk < BK; kk++) {
                float a[8], b[4];
                *(float4*)&a[0] = *(const float4*)&As[kk][ty * 8];
                *(float4*)&a[4] = *(const float4*)&As[kk][ty * 8 + 4];
                *(float4*)&b[0] = *(const float4*)&Bs[kk][tx * 4];
#pragma unroll
                for (int i = 0; i < 8; i++)
#pragma unroll
                    for (int j = 0; j < 4; j++) acc[i][j] += a[i] * b[j];
            }
            __syncthreads();
        }
    }

    // epilogue
#pragma unroll
    for (int i = 0; i < 8; i++) {
        int m = m0 + ty * 8 + i;
        if (m < M) {
            int n = n0 + tx * 4;
            float4 o;
            o.x = acc[i][0]; o.y = acc[i][1]; o.z = acc[i][2]; o.w = acc[i][3];
            if (bias) {
                const float4 bv = *(const float4*)(bias + n);
                o.x += bv.x; o.y += bv.y; o.z += bv.z; o.w += bv.w;
            }
            if (D) {
                const float4 dv = *(const float4*)(D + (size_t)m * N + n);
                o.x += dv.x; o.y += dv.y; o.z += dv.z; o.w += dv.w;
            }
            if (relu) {
                o.x = fmaxf(o.x, 0.f); o.y = fmaxf(o.y, 0.f);
                o.z = fmaxf(o.z, 0.f); o.w = fmaxf(o.w, 0.f);
            }
            *(float4*)(C + (size_t)m * N + n) = o;
        }
    }
}

// ---------------- launcher -----------------------------------------------------
extern "C" void kernel_launch(void* const* d_in, const int* in_sizes, int n_in,
                              void* d_out, int out_size) {
    const float* x   = (const float*)d_in[0];
    const int*   ei  = (const int*)d_in[1];   // int32 OR int64 (detected on device)
    const float* W1l = (const float*)d_in[2];
    const float* b1  = (const float*)d_in[3];
    const float* W1r = (const float*)d_in[4];
    const float* W2l = (const float*)d_in[5];
    const float* b2  = (const float*)d_in[6];
    const float* W2r = (const float*)d_in[7];
    float* out = (float*)d_out;

    float *aggA, *h, *p, *agg2;
    cudaGetSymbolAddress((void**)&aggA, g_aggA);
    cudaGetSymbolAddress((void**)&h,    g_h);
    cudaGetSymbolAddress((void**)&p,    g_p);
    cudaGetSymbolAddress((void**)&agg2, g_agg2);

    // Edge dtype detection + normalization to int32
    detect_kernel<<<1, 32>>>(ei);
    convert_kernel<<<(EE + 255) / 256, 256>>>(ei);

    // CSR build (shared by both layers)
    zero_cnt_kernel<<<(NN + 255) / 256, 256>>>();
    hist_kernel<<<(EE + 255) / 256, 256>>>();
    scan_kernel<<<1, 1024>>>();
    fill_kernel<<<(EE + 255) / 256, 256>>>();

    // Layer 1: aggregate x (128 dims), then h = relu(aggA@W1l + x@W1r + b1)
    agg_kernel<1><<<(NN + 7) / 8, 256>>>(x, aggA);
    {
        dim3 grid(FHID / 64, (NN + 127) / 128);
        gemm_kernel<<<grid, 256>>>(aggA, W1l, x, W1r, b1, nullptr, h,
                                   NN, FHID, FIN, /*relu=*/1);
    }

    // Layer 2: p = h@W2l  (GEMM before aggregation: mean commutes with linear)
    {
        dim3 grid(FOUT / 64, (NN + 127) / 128);
        gemm_kernel<<<grid, 256>>>(h, W2l, nullptr, nullptr, nullptr, nullptr, p,
                                   NN, FOUT, FHID, /*relu=*/0);
    }
    // agg2 = scatter_mean(p)  (256 dims)
    agg_kernel<2><<<(NN + 7) / 8, 256>>>(p, agg2);
    // out = h@W2r + b2 + agg2
    {
        dim3 grid(FOUT / 64, (NN + 127) / 128);
        gemm_kernel<<<grid, 256>>>(h, W2r, nullptr, nullptr, b2, agg2, out,
                                   NN, FOUT, FHID, /*relu=*/0);
    }
}

// round 6
// speedup vs baseline: 1.7701x; 1.7701x over previous
#include <cuda_runtime.h>
#include <cstdint>

// Problem constants (fixed by the dataset generator).
#define NN   40000
#define EE   640000
#define FIN  128
#define FHID 512
#define FOUT 256

// ---------------- scratch (static device globals; no allocation allowed) ----
__device__ int   g_is64;
__device__ int   g_src[EE];
__device__ int   g_dst[EE];
__device__ int   g_cnt[NN];
__device__ int   g_rowptr[NN + 1];
__device__ int   g_cursor[NN];
__device__ int   g_col[EE];
__device__ float g_aggA[(size_t)NN * FIN];   // mean-aggregated x        (20 MB)
__device__ float g_h   [(size_t)NN * FHID];  // layer-1 output           (82 MB)
__device__ float g_p   [(size_t)NN * FOUT];  // h @ W2l                  (40 MB)
__device__ float g_agg2[(size_t)NN * FOUT];  // mean-aggregated p        (40 MB)
// transposed weights [N,K] so the GEMM B operand is K-major (col-major B)
__device__ float g_Wt1l[FHID * FIN];
__device__ float g_Wt1r[FHID * FIN];
__device__ float g_Wt2l[FOUT * FHID];
__device__ float g_Wt2r[FOUT * FHID];

// ---------------- edge dtype detection + conversion ---------------------------
__global__ void detect_kernel(const int* __restrict__ ei32) {
    if (threadIdx.x == 0 && blockIdx.x == 0) {
        int all0 = 1;
        for (int i = 0; i < 64; i++)
            if (ei32[2 * i + 1] != 0) all0 = 0;
        g_is64 = all0;
    }
}
__global__ void convert_kernel(const int* __restrict__ ei32) {
    int e = blockIdx.x * blockDim.x + threadIdx.x;
    if (e >= EE) return;
    int s, d;
    if (g_is64) {
        const long long* ei64 = (const long long*)ei32;
        s = (int)ei64[e];
        d = (int)ei64[EE + e];
    } else {
        s = ei32[e];
        d = ei32[EE + e];
    }
    g_src[e] = s;
    g_dst[e] = d;
}

// ---------------- CSR build --------------------------------------------------
__global__ void zero_cnt_kernel() {
    int i = blockIdx.x * blockDim.x + threadIdx.x;
    if (i < NN) g_cnt[i] = 0;
}
__global__ void hist_kernel() {
    int e = blockIdx.x * blockDim.x + threadIdx.x;
    if (e < EE) atomicAdd(&g_cnt[g_dst[e]], 1);
}
__global__ void scan_kernel() {
    const int T = 1024;
    const int CH = (NN + T - 1) / T;
    __shared__ int s[T];
    int t = threadIdx.x;
    int base = t * CH;
    int sum = 0;
    for (int j = 0; j < CH; j++) {
        int i = base + j;
        if (i < NN) sum += g_cnt[i];
    }
    s[t] = sum;
    __syncthreads();
    for (int off = 1; off < T; off <<= 1) {
        int v = (t >= off) ? s[t - off] : 0;
        __syncthreads();
        s[t] += v;
        __syncthreads();
    }
    int run = s[t] - sum;
    for (int j = 0; j < CH; j++) {
        int i = base + j;
        if (i < NN) {
            g_rowptr[i] = run;
            g_cursor[i] = run;
            run += g_cnt[i];
        }
    }
    if (t == 0) g_rowptr[NN] = EE;
}
__global__ void fill_kernel() {
    int e = blockIdx.x * blockDim.x + threadIdx.x;
    if (e < EE) {
        int d   = g_dst[e];
        int pos = atomicAdd(&g_cursor[d], 1);
        g_col[pos] = g_src[e];
    }
}

// ---------------- weight transpose [K,N] -> [N,K] -----------------------------
__global__ void transpose_kernel(const float* __restrict__ W,
                                 float* __restrict__ Wt, int K, int N) {
    int idx = blockIdx.x * blockDim.x + threadIdx.x;
    if (idx < K * N) {
        int k = idx / N, n = idx % N;
        Wt[(size_t)n * K + k] = W[idx];
    }
}

// ---------------- mean aggregation over CSR (unroll-2 for MLP) ----------------
template <int VPL>
__global__ void agg_kernel(const float* __restrict__ feat,
                           float* __restrict__ out) {
    int node = blockIdx.x * (blockDim.x >> 5) + (threadIdx.x >> 5);
    if (node >= NN) return;
    int lane = threadIdx.x & 31;
    int beg = g_rowptr[node];
    int end = g_rowptr[node + 1];

    const int F = VPL * 128;
    float4 acc[VPL];
#pragma unroll
    for (int v = 0; v < VPL; v++) acc[v] = make_float4(0.f, 0.f, 0.f, 0.f);

    int j = beg;
    for (; j + 1 < end; j += 2) {
        int s0 = __ldg(&g_col[j]);
        int s1 = __ldg(&g_col[j + 1]);
        const float4* r0 = (const float4*)(feat + (size_t)s0 * F);
        const float4* r1 = (const float4*)(feat + (size_t)s1 * F);
#pragma unroll
        for (int v = 0; v < VPL; v++) {
            float4 a = r0[lane + v * 32];
            float4 b = r1[lane + v * 32];
            acc[v].x += a.x + b.x; acc[v].y += a.y + b.y;
            acc[v].z += a.z + b.z; acc[v].w += a.w + b.w;
        }
    }
    if (j < end) {
        int s0 = __ldg(&g_col[j]);
        const float4* r0 = (const float4*)(feat + (size_t)s0 * F);
#pragma unroll
        for (int v = 0; v < VPL; v++) {
            float4 a = r0[lane + v * 32];
            acc[v].x += a.x; acc[v].y += a.y; acc[v].z += a.z; acc[v].w += a.w;
        }
    }
    float inv = 1.0f / (float)max(end - beg, 1);
    float4* o = (float4*)(out + (size_t)node * F);
#pragma unroll
    for (int v = 0; v < VPL; v++) {
        acc[v].x *= inv; acc[v].y *= inv; acc[v].z *= inv; acc[v].w *= inv;
        o[lane + v * 32] = acc[v];
    }
}

// ================= tf32 mma.sync GEMM (sm_80+ baseline ISA) ===================
// C[M,N] = A1[M,K1] @ B1t[N,K1]^T (+ A2 @ B2t^T) (+bias) (+Dres) (relu?)
// BM=128, BN=128, BK=32, 256 threads (8 warps, warp tile 32x64),
// cp.async double-buffered SMEM, padded rows (36 floats) for conflict-free LDS.
#define G_BM 128
#define G_BN 128
#define G_BK 32
#define G_PAD_STRIDE 36                       // floats per smem row
#define G_STAGE_FLOATS (128 * G_PAD_STRIDE)   // one operand tile
#define G_STAGE_BYTES (G_STAGE_FLOATS * 4)    // 18432 B
#define G_SMEM_SZ (4 * G_STAGE_BYTES)         // A+B, 2 stages = 73728 B

__device__ __forceinline__ uint32_t smem_u32(const void* p) {
    uint32_t a;
    asm("{ .reg .u64 t; cvta.to.shared.u64 t, %1; cvt.u32.u64 %0, t; }"
        : "=r"(a) : "l"(p));
    return a;
}
__device__ __forceinline__ void cp_async16(uint32_t dst, const void* src, int src_bytes) {
    asm volatile("cp.async.ca.shared.global [%0], [%1], 16, %2;"
                 :: "r"(dst), "l"(src), "r"(src_bytes) : "memory");
}
__device__ __forceinline__ void cp_commit() {
    asm volatile("cp.async.commit_group;" ::: "memory");
}
template <int NPEND>
__device__ __forceinline__ void cp_wait() {
    asm volatile("cp.async.wait_group %0;" :: "n"(NPEND) : "memory");
}
__device__ __forceinline__ uint32_t f2tf32(float f) {
    uint32_t u;
    asm("cvt.rna.tf32.f32 %0, %1;" : "=r"(u) : "f"(f));
    return u;
}
__device__ __forceinline__ void mma_tf32(float* d, const uint32_t* a, const uint32_t* b) {
    asm volatile(
        "mma.sync.aligned.m16n8k8.row.col.f32.tf32.tf32.f32 "
        "{%0,%1,%2,%3}, {%4,%5,%6,%7}, {%8,%9}, {%0,%1,%2,%3};"
        : "+f"(d[0]), "+f"(d[1]), "+f"(d[2]), "+f"(d[3])
        : "r"(a[0]), "r"(a[1]), "r"(a[2]), "r"(a[3]), "r"(b[0]), "r"(b[1]));
}

// Issue cp.async loads for one operand tile: 128 rows x 32 floats.
// rows beyond row_lim are zero-filled (src clamped, src_bytes = 0).
__device__ __forceinline__ void gemm_issue_tile(
    const float* __restrict__ src, int row0, int row_lim, int K, int k0,
    uint32_t dst_base, int tid) {
#pragma unroll
    for (int u = 0; u < 4; u++) {
        int id  = u * 256 + tid;      // 16B chunk id in [0,1024)
        int row = id >> 3;
        int c   = id & 7;
        int gr  = row0 + row;
        int ok  = gr < row_lim;
        const float* s = src + (size_t)(ok ? gr : (row_lim - 1)) * K + k0 + c * 4;
        cp_async16(dst_base + row * (G_PAD_STRIDE * 4) + c * 16, s, ok ? 16 : 0);
    }
}

__global__ void __launch_bounds__(256)
gemm_tf32_kernel(const float* __restrict__ A1, const float* __restrict__ B1t, int K1,
                 const float* __restrict__ A2, const float* __restrict__ B2t, int K2,
                 const float* __restrict__ bias, const float* __restrict__ Dres,
                 float* __restrict__ C, int M, int N, int relu) {
    extern __shared__ float smem[];
    uint32_t sb = smem_u32(smem);

    int tid  = threadIdx.x;
    int wid  = tid >> 5;
    int lane = tid & 31;
    int wm   = wid & 3;     // warp row  (4 x 32 = 128)
    int wn   = wid >> 2;    // warp col  (2 x 64 = 128)
    int m0 = blockIdx.y * G_BM;
    int n0 = blockIdx.x * G_BN;

    const int kt1 = K1 >> 5;
    const int KT  = kt1 + (K2 >> 5);

    float acc[2][8][4];
#pragma unroll
    for (int i = 0; i < 2; i++)
#pragma unroll
        for (int j = 0; j < 8; j++)
#pragma unroll
            for (int q = 0; q < 4; q++) acc[i][j][q] = 0.f;

    // stage s: A at s*2*STAGE, B at s*2*STAGE + STAGE
    auto issue = [&](int kt) {
        const float* A;
        const float* B;
        int K, kk;
        if (kt < kt1) { A = A1; B = B1t; K = K1; kk = kt; }
        else          { A = A2; B = B2t; K = K2; kk = kt - kt1; }
        int s = kt & 1;
        uint32_t aB = sb + (uint32_t)(s * 2 * G_STAGE_BYTES);
        uint32_t bB = aB + G_STAGE_BYTES;
        gemm_issue_tile(A, m0, M, K, kk * G_BK, aB, tid);
        gemm_issue_tile(B, n0, N, K, kk * G_BK, bB, tid);
    };

    issue(0);
    cp_commit();

    int r_lo = (lane >> 2);   // 0..7
    int k_lo = (lane & 3);    // 0..3

    for (int kt = 0; kt < KT; kt++) {
        if (kt + 1 < KT) {
            issue(kt + 1);
            cp_commit();
            cp_wait<1>();
        } else {
            cp_wait<0>();
        }
        __syncthreads();

        int s = kt & 1;
        const float* As = smem + (size_t)s * 2 * G_STAGE_FLOATS;
        const float* Bs = As + G_STAGE_FLOATS;

#pragma unroll
        for (int ks = 0; ks < 4; ks++) {
            int k = ks * 8 + k_lo;
            uint32_t af[2][4];
#pragma unroll
            for (int tm = 0; tm < 2; tm++) {
                int r = wm * 32 + tm * 16 + r_lo;
                af[tm][0] = f2tf32(As[r * G_PAD_STRIDE + k]);
                af[tm][1] = f2tf32(As[(r + 8) * G_PAD_STRIDE + k]);
                af[tm][2] = f2tf32(As[r * G_PAD_STRIDE + k + 4]);
                af[tm][3] = f2tf32(As[(r + 8) * G_PAD_STRIDE + k + 4]);
            }
            uint32_t bf[8][2];
#pragma unroll
            for (int tn = 0; tn < 8; tn++) {
                int n = wn * 64 + tn * 8 + r_lo;
                bf[tn][0] = f2tf32(Bs[n * G_PAD_STRIDE + k]);
                bf[tn][1] = f2tf32(Bs[n * G_PAD_STRIDE + k + 4]);
            }
#pragma unroll
            for (int tm = 0; tm < 2; tm++)
#pragma unroll
                for (int tn = 0; tn < 8; tn++)
                    mma_tf32(acc[tm][tn], af[tm], bf[tn]);
        }
        __syncthreads();
    }

    // epilogue: fragment (tm,tn): rows r0/r0+8, cols n..n+1 (float2)
#pragma unroll
    for (int tm = 0; tm < 2; tm++) {
#pragma unroll
        for (int half = 0; half < 2; half++) {
            int m = m0 + wm * 32 + tm * 16 + half * 8 + r_lo;
            if (m >= M) continue;
#pragma unroll
            for (int tn = 0; tn < 8; tn++) {
                int n = n0 + wn * 64 + tn * 8 + k_lo * 2;
                float2 o;
                o.x = acc[tm][tn][half * 2 + 0];
                o.y = acc[tm][tn][half * 2 + 1];
                if (bias) {
                    float2 bv = *(const float2*)(bias + n);
                    o.x += bv.x; o.y += bv.y;
                }
                if (Dres) {
                    float2 dv = *(const float2*)(Dres + (size_t)m * N + n);
                    o.x += dv.x; o.y += dv.y;
                }
                if (relu) {
                    o.x = fmaxf(o.x, 0.f);
                    o.y = fmaxf(o.y, 0.f);
                }
                *(float2*)(C + (size_t)m * N + n) = o;
            }
        }
    }
}

// ---------------- launcher -----------------------------------------------------
extern "C" void kernel_launch(void* const* d_in, const int* in_sizes, int n_in,
                              void* d_out, int out_size) {
    const float* x   = (const float*)d_in[0];
    const int*   ei  = (const int*)d_in[1];   // int32 OR int64 (device-detected)
    const float* W1l = (const float*)d_in[2];
    const float* b1  = (const float*)d_in[3];
    const float* W1r = (const float*)d_in[4];
    const float* W2l = (const float*)d_in[5];
    const float* b2  = (const float*)d_in[6];
    const float* W2r = (const float*)d_in[7];
    float* out = (float*)d_out;

    float *aggA, *h, *p, *agg2, *Wt1l, *Wt1r, *Wt2l, *Wt2r;
    cudaGetSymbolAddress((void**)&aggA, g_aggA);
    cudaGetSymbolAddress((void**)&h,    g_h);
    cudaGetSymbolAddress((void**)&p,    g_p);
    cudaGetSymbolAddress((void**)&agg2, g_agg2);
    cudaGetSymbolAddress((void**)&Wt1l, g_Wt1l);
    cudaGetSymbolAddress((void**)&Wt1r, g_Wt1r);
    cudaGetSymbolAddress((void**)&Wt2l, g_Wt2l);
    cudaGetSymbolAddress((void**)&Wt2r, g_Wt2r);

    static int smem_set = 0;
    if (!smem_set) {
        cudaFuncSetAttribute(gemm_tf32_kernel,
                             cudaFuncAttributeMaxDynamicSharedMemorySize, G_SMEM_SZ);
        smem_set = 1;
    }

    // Edge dtype detection + normalization to int32
    detect_kernel<<<1, 32>>>(ei);
    convert_kernel<<<(EE + 255) / 256, 256>>>(ei);

    // CSR build
    zero_cnt_kernel<<<(NN + 255) / 256, 256>>>();
    hist_kernel<<<(EE + 255) / 256, 256>>>();
    scan_kernel<<<1, 1024>>>();
    fill_kernel<<<(EE + 255) / 256, 256>>>();

    // Weight transposes (tiny)
    transpose_kernel<<<(FIN * FHID + 255) / 256, 256>>>(W1l, Wt1l, FIN, FHID);
    transpose_kernel<<<(FIN * FHID + 255) / 256, 256>>>(W1r, Wt1r, FIN, FHID);
    transpose_kernel<<<(FHID * FOUT + 255) / 256, 256>>>(W2l, Wt2l, FHID, FOUT);
    transpose_kernel<<<(FHID * FOUT + 255) / 256, 256>>>(W2r, Wt2r, FHID, FOUT);

    // Layer 1: aggregate x, then h = relu(aggA@W1l + x@W1r + b1)
    agg_kernel<1><<<(NN + 7) / 8, 256>>>(x, aggA);
    {
        dim3 grid(FHID / G_BN, (NN + G_BM - 1) / G_BM);
        gemm_tf32_kernel<<<grid, 256, G_SMEM_SZ>>>(
            aggA, Wt1l, FIN, x, Wt1r, FIN, b1, nullptr, h, NN, FHID, 1);
    }
    // Layer 2: p = h@W2l (GEMM before aggregation: mean commutes with linear)
    {
        dim3 grid(FOUT / G_BN, (NN + G_BM - 1) / G_BM);
        gemm_tf32_kernel<<<grid, 256, G_SMEM_SZ>>>(
            h, Wt2l, FHID, nullptr, nullptr, 0, nullptr, nullptr, p, NN, FOUT, 0);
    }
    // agg2 = scatter_mean(p)
    agg_kernel<2><<<(NN + 7) / 8, 256>>>(p, agg2);
    // out = h@W2r + b2 + agg2
    {
        dim3 grid(FOUT / G_BN, (NN + G_BM - 1) / G_BM);
        gemm_tf32_kernel<<<grid, 256, G_SMEM_SZ>>>(
            h, Wt2r, FHID, nullptr, nullptr, 0, b2, agg2, out, NN, FOUT, 0);
    }
}

// round 7
// speedup vs baseline: 2.2152x; 1.2514x over previous
#include <cuda_runtime.h>
#include <cstdint>

// Problem constants (fixed by the dataset generator).
#define NN   40000
#define EE   640000
#define FIN  128
#define FHID 512
#define FOUT 256

// ---------------- scratch (static device globals; no allocation allowed) ----
__device__ int   g_is64;
__device__ int   g_cnt[NN];
__device__ int   g_rowptr[NN + 1];
__device__ int   g_cursor[NN];
__device__ int   g_col[EE];
__device__ float g_xr  [(size_t)NN * FIN];   // tf32-rounded copy of x   (20 MB)
__device__ float g_aggA[(size_t)NN * FIN];   // mean-aggregated x        (20 MB)
__device__ float g_h   [(size_t)NN * FHID];  // layer-1 output           (82 MB)
__device__ float g_p   [(size_t)NN * FOUT];  // h @ W2l                  (40 MB)
__device__ float g_agg2[(size_t)NN * FOUT];  // mean-aggregated p        (40 MB)
// transposed (and tf32-rounded) weights [N,K]
__device__ float g_Wt1l[FHID * FIN];
__device__ float g_Wt1r[FHID * FIN];
__device__ float g_Wt2l[FOUT * FHID];
__device__ float g_Wt2r[FOUT * FHID];

__device__ __forceinline__ float tf32r(float f) {
    uint32_t u;
    asm("cvt.rna.tf32.f32 %0, %1;" : "=r"(u) : "f"(f));
    return __uint_as_float(u);
}

// ---------------- edge dtype detection + direct readers -----------------------
__global__ void detect_kernel(const int* __restrict__ ei32) {
    if (threadIdx.x == 0 && blockIdx.x == 0) {
        int all0 = 1;
        for (int i = 0; i < 64; i++)
            if (ei32[2 * i + 1] != 0) all0 = 0;
        g_is64 = all0;
    }
}
__device__ __forceinline__ int edge_at(const int* __restrict__ ei, int is64, size_t idx) {
    return is64 ? (int)((const long long*)ei)[idx] : ei[idx];
}

// ---------------- CSR build --------------------------------------------------
__global__ void zero_cnt_kernel() {
    int i = blockIdx.x * blockDim.x + threadIdx.x;
    if (i < NN) g_cnt[i] = 0;
}
__global__ void hist_kernel(const int* __restrict__ ei) {
    int e = blockIdx.x * blockDim.x + threadIdx.x;
    if (e < EE) atomicAdd(&g_cnt[edge_at(ei, g_is64, (size_t)EE + e)], 1);
}
__global__ void scan_kernel() {
    const int T = 1024;
    const int CH = (NN + T - 1) / T;
    __shared__ int s[T];
    int t = threadIdx.x;
    int base = t * CH;
    int sum = 0;
    for (int j = 0; j < CH; j++) {
        int i = base + j;
        if (i < NN) sum += g_cnt[i];
    }
    s[t] = sum;
    __syncthreads();
    for (int off = 1; off < T; off <<= 1) {
        int v = (t >= off) ? s[t - off] : 0;
        __syncthreads();
        s[t] += v;
        __syncthreads();
    }
    int run = s[t] - sum;
    for (int j = 0; j < CH; j++) {
        int i = base + j;
        if (i < NN) {
            g_rowptr[i] = run;
            g_cursor[i] = run;
            run += g_cnt[i];
        }
    }
    if (t == 0) g_rowptr[NN] = EE;
}
__global__ void fill_kernel(const int* __restrict__ ei) {
    int e = blockIdx.x * blockDim.x + threadIdx.x;
    if (e < EE) {
        int is64 = g_is64;
        int d = edge_at(ei, is64, (size_t)EE + e);
        int s = edge_at(ei, is64, (size_t)e);
        int pos = atomicAdd(&g_cursor[d], 1);
        g_col[pos] = s;
    }
}

// ---------------- weight transpose [K,N] -> [N,K] (+tf32 round) ---------------
__global__ void transpose_kernel(const float* __restrict__ W,
                                 float* __restrict__ Wt, int K, int N) {
    int idx = blockIdx.x * blockDim.x + threadIdx.x;
    if (idx < K * N) {
        int k = idx / N, n = idx % N;
        Wt[(size_t)n * K + k] = tf32r(W[idx]);
    }
}

// ---------------- round x into g_xr -------------------------------------------
__global__ void round_x_kernel(const float* __restrict__ x, float* __restrict__ xr) {
    int i = blockIdx.x * blockDim.x + threadIdx.x;
    const int TOT = NN * FIN;
    if (i < TOT) {
        float4 v = *(const float4*)(x + (size_t)i * 4);
        float4 o;
        o.x = tf32r(v.x); o.y = tf32r(v.y); o.z = tf32r(v.z); o.w = tf32r(v.w);
        if (i * 4 < TOT) *(float4*)(xr + (size_t)i * 4) = o;
    }
}

// ---------------- mean aggregation over CSR (unroll-4 for MLP) ----------------
// One warp per node; lane owns VPL float4 chunks. ROUND: tf32-round outputs.
template <int VPL, int ROUND>
__global__ void agg_kernel(const float* __restrict__ feat,
                           float* __restrict__ out) {
    int node = blockIdx.x * (blockDim.x >> 5) + (threadIdx.x >> 5);
    if (node >= NN) return;
    int lane = threadIdx.x & 31;
    int beg = g_rowptr[node];
    int end = g_rowptr[node + 1];

    const int F = VPL * 128;
    float4 acc[VPL];
#pragma unroll
    for (int v = 0; v < VPL; v++) acc[v] = make_float4(0.f, 0.f, 0.f, 0.f);

    int j = beg;
    for (; j + 3 < end; j += 4) {
        int s0 = __ldg(&g_col[j]);
        int s1 = __ldg(&g_col[j + 1]);
        int s2 = __ldg(&g_col[j + 2]);
        int s3 = __ldg(&g_col[j + 3]);
        const float4* r0 = (const float4*)(feat + (size_t)s0 * F);
        const float4* r1 = (const float4*)(feat + (size_t)s1 * F);
        const float4* r2 = (const float4*)(feat + (size_t)s2 * F);
        const float4* r3 = (const float4*)(feat + (size_t)s3 * F);
#pragma unroll
        for (int v = 0; v < VPL; v++) {
            float4 a = r0[lane + v * 32];
            float4 b = r1[lane + v * 32];
            float4 c = r2[lane + v * 32];
            float4 d = r3[lane + v * 32];
            acc[v].x += (a.x + b.x) + (c.x + d.x);
            acc[v].y += (a.y + b.y) + (c.y + d.y);
            acc[v].z += (a.z + b.z) + (c.z + d.z);
            acc[v].w += (a.w + b.w) + (c.w + d.w);
        }
    }
    for (; j < end; j++) {
        int s0 = __ldg(&g_col[j]);
        const float4* r0 = (const float4*)(feat + (size_t)s0 * F);
#pragma unroll
        for (int v = 0; v < VPL; v++) {
            float4 a = r0[lane + v * 32];
            acc[v].x += a.x; acc[v].y += a.y; acc[v].z += a.z; acc[v].w += a.w;
        }
    }
    float inv = 1.0f / (float)max(end - beg, 1);
    float4* o = (float4*)(out + (size_t)node * F);
#pragma unroll
    for (int v = 0; v < VPL; v++) {
        acc[v].x *= inv; acc[v].y *= inv; acc[v].z *= inv; acc[v].w *= inv;
        if (ROUND) {
            acc[v].x = tf32r(acc[v].x); acc[v].y = tf32r(acc[v].y);
            acc[v].z = tf32r(acc[v].z); acc[v].w = tf32r(acc[v].w);
        }
        o[lane + v * 32] = acc[v];
    }
}

// ================= tf32 mma.sync GEMM (sm_80+ baseline ISA) ===================
// All A/B operands are PRE-ROUNDED to tf32 in global memory, so the mainloop
// feeds raw fp32 bits to mma (bit-identical to cvt.rna at use site, zero CVTs).
#define G_BM 128
#define G_BN 128
#define G_BK 32
#define G_PAD_STRIDE 36
#define G_STAGE_FLOATS (128 * G_PAD_STRIDE)
#define G_STAGE_BYTES (G_STAGE_FLOATS * 4)
#define G_SMEM_SZ (4 * G_STAGE_BYTES)

__device__ __forceinline__ uint32_t smem_u32(const void* p) {
    uint32_t a;
    asm("{ .reg .u64 t; cvta.to.shared.u64 t, %1; cvt.u32.u64 %0, t; }"
        : "=r"(a) : "l"(p));
    return a;
}
__device__ __forceinline__ void cp_async16(uint32_t dst, const void* src, int src_bytes) {
    asm volatile("cp.async.ca.shared.global [%0], [%1], 16, %2;"
                 :: "r"(dst), "l"(src), "r"(src_bytes) : "memory");
}
__device__ __forceinline__ void cp_commit() {
    asm volatile("cp.async.commit_group;" ::: "memory");
}
template <int NPEND>
__device__ __forceinline__ void cp_wait() {
    asm volatile("cp.async.wait_group %0;" :: "n"(NPEND) : "memory");
}
__device__ __forceinline__ void mma_tf32(float* d, const uint32_t* a, const uint32_t* b) {
    asm volatile(
        "mma.sync.aligned.m16n8k8.row.col.f32.tf32.tf32.f32 "
        "{%0,%1,%2,%3}, {%4,%5,%6,%7}, {%8,%9}, {%0,%1,%2,%3};"
        : "+f"(d[0]), "+f"(d[1]), "+f"(d[2]), "+f"(d[3])
        : "r"(a[0]), "r"(a[1]), "r"(a[2]), "r"(a[3]), "r"(b[0]), "r"(b[1]));
}

__device__ __forceinline__ void gemm_issue_tile(
    const float* __restrict__ src, int row0, int row_lim, int K, int k0,
    uint32_t dst_base, int tid) {
#pragma unroll
    for (int u = 0; u < 4; u++) {
        int id  = u * 256 + tid;
        int row = id >> 3;
        int c   = id & 7;
        int gr  = row0 + row;
        int ok  = gr < row_lim;
        const float* s = src + (size_t)(ok ? gr : (row_lim - 1)) * K + k0 + c * 4;
        cp_async16(dst_base + row * (G_PAD_STRIDE * 4) + c * 16, s, ok ? 16 : 0);
    }
}

__global__ void __launch_bounds__(256)
gemm_tf32_kernel(const float* __restrict__ A1, const float* __restrict__ B1t, int K1,
                 const float* __restrict__ A2, const float* __restrict__ B2t, int K2,
                 const float* __restrict__ bias, const float* __restrict__ Dres,
                 float* __restrict__ C, int M, int N, int relu, int round_out) {
    extern __shared__ float smem[];
    uint32_t sb = smem_u32(smem);

    int tid  = threadIdx.x;
    int lane = tid & 31;
    int wid  = tid >> 5;
    int wm   = wid & 3;
    int wn   = wid >> 2;
    int m0 = blockIdx.y * G_BM;
    int n0 = blockIdx.x * G_BN;

    const int kt1 = K1 >> 5;
    const int KT  = kt1 + (K2 >> 5);

    float acc[2][8][4];
#pragma unroll
    for (int i = 0; i < 2; i++)
#pragma unroll
        for (int j = 0; j < 8; j++)
#pragma unroll
            for (int q = 0; q < 4; q++) acc[i][j][q] = 0.f;

    auto issue = [&](int kt) {
        const float* A;
        const float* B;
        int K, kk;
        if (kt < kt1) { A = A1; B = B1t; K = K1; kk = kt; }
        else          { A = A2; B = B2t; K = K2; kk = kt - kt1; }
        int s = kt & 1;
        uint32_t aB = sb + (uint32_t)(s * 2 * G_STAGE_BYTES);
        uint32_t bB = aB + G_STAGE_BYTES;
        gemm_issue_tile(A, m0, M, K, kk * G_BK, aB, tid);
        gemm_issue_tile(B, n0, N, K, kk * G_BK, bB, tid);
    };

    issue(0);
    cp_commit();

    int r_lo = (lane >> 2);
    int k_lo = (lane & 3);

    for (int kt = 0; kt < KT; kt++) {
        if (kt + 1 < KT) {
            issue(kt + 1);
            cp_commit();
            cp_wait<1>();
        } else {
            cp_wait<0>();
        }
        __syncthreads();

        int s = kt & 1;
        const uint32_t* As = (const uint32_t*)(smem + (size_t)s * 2 * G_STAGE_FLOATS);
        const uint32_t* Bs = As + G_STAGE_FLOATS;

#pragma unroll
        for (int ks = 0; ks < 4; ks++) {
            int k = ks * 8 + k_lo;
            uint32_t af[2][4];
#pragma unroll
            for (int tm = 0; tm < 2; tm++) {
                int r = wm * 32 + tm * 16 + r_lo;
                af[tm][0] = As[r * G_PAD_STRIDE + k];
                af[tm][1] = As[(r + 8) * G_PAD_STRIDE + k];
                af[tm][2] = As[r * G_PAD_STRIDE + k + 4];
                af[tm][3] = As[(r + 8) * G_PAD_STRIDE + k + 4];
            }
            uint32_t bf[8][2];
#pragma unroll
            for (int tn = 0; tn < 8; tn++) {
                int n = wn * 64 + tn * 8 + r_lo;
                bf[tn][0] = Bs[n * G_PAD_STRIDE + k];
                bf[tn][1] = Bs[n * G_PAD_STRIDE + k + 4];
            }
#pragma unroll
            for (int tm = 0; tm < 2; tm++)
#pragma unroll
                for (int tn = 0; tn < 8; tn++)
                    mma_tf32(acc[tm][tn], af[tm], bf[tn]);
        }
        __syncthreads();
    }

    // epilogue
#pragma unroll
    for (int tm = 0; tm < 2; tm++) {
#pragma unroll
        for (int half = 0; half < 2; half++) {
            int m = m0 + wm * 32 + tm * 16 + half * 8 + r_lo;
            if (m >= M) continue;
#pragma unroll
            for (int tn = 0; tn < 8; tn++) {
                int n = n0 + wn * 64 + tn * 8 + k_lo * 2;
                float2 o;
                o.x = acc[tm][tn][half * 2 + 0];
                o.y = acc[tm][tn][half * 2 + 1];
                if (bias) {
                    float2 bv = *(const float2*)(bias + n);
                    o.x += bv.x; o.y += bv.y;
                }
                if (Dres) {
                    float2 dv = *(const float2*)(Dres + (size_t)m * N + n);
                    o.x += dv.x; o.y += dv.y;
                }
                if (relu) {
                    o.x = fmaxf(o.x, 0.f);
                    o.y = fmaxf(o.y, 0.f);
                }
                if (round_out) {
                    o.x = tf32r(o.x);
                    o.y = tf32r(o.y);
                }
                *(float2*)(C + (size_t)m * N + n) = o;
            }
        }
    }
}

// ---------------- launcher -----------------------------------------------------
extern "C" void kernel_launch(void* const* d_in, const int* in_sizes, int n_in,
                              void* d_out, int out_size) {
    const float* x   = (const float*)d_in[0];
    const int*   ei  = (const int*)d_in[1];   // int32 OR int64 (device-detected)
    const float* W1l = (const float*)d_in[2];
    const float* b1  = (const float*)d_in[3];
    const float* W1r = (const float*)d_in[4];
    const float* W2l = (const float*)d_in[5];
    const float* b2  = (const float*)d_in[6];
    const float* W2r = (const float*)d_in[7];
    float* out = (float*)d_out;

    float *xr, *aggA, *h, *p, *agg2, *Wt1l, *Wt1r, *Wt2l, *Wt2r;
    cudaGetSymbolAddress((void**)&xr,   g_xr);
    cudaGetSymbolAddress((void**)&aggA, g_aggA);
    cudaGetSymbolAddress((void**)&h,    g_h);
    cudaGetSymbolAddress((void**)&p,    g_p);
    cudaGetSymbolAddress((void**)&agg2, g_agg2);
    cudaGetSymbolAddress((void**)&Wt1l, g_Wt1l);
    cudaGetSymbolAddress((void**)&Wt1r, g_Wt1r);
    cudaGetSymbolAddress((void**)&Wt2l, g_Wt2l);
    cudaGetSymbolAddress((void**)&Wt2r, g_Wt2r);

    static int smem_set = 0;
    if (!smem_set) {
        cudaFuncSetAttribute(gemm_tf32_kernel,
                             cudaFuncAttributeMaxDynamicSharedMemorySize, G_SMEM_SZ);
        smem_set = 1;
    }

    // Edge dtype detection, CSR build
    detect_kernel<<<1, 32>>>(ei);
    zero_cnt_kernel<<<(NN + 255) / 256, 256>>>();
    hist_kernel<<<(EE + 255) / 256, 256>>>(ei);
    scan_kernel<<<1, 1024>>>();
    fill_kernel<<<(EE + 255) / 256, 256>>>(ei);

    // Pre-rounded operands
    round_x_kernel<<<(NN * FIN / 4 + 255) / 256, 256>>>(x, xr);
    transpose_kernel<<<(FIN * FHID + 255) / 256, 256>>>(W1l, Wt1l, FIN, FHID);
    transpose_kernel<<<(FIN * FHID + 255) / 256, 256>>>(W1r, Wt1r, FIN, FHID);
    transpose_kernel<<<(FHID * FOUT + 255) / 256, 256>>>(W2l, Wt2l, FHID, FOUT);
    transpose_kernel<<<(FHID * FOUT + 255) / 256, 256>>>(W2r, Wt2r, FHID, FOUT);

    // Layer 1: aggregate x (rounded output), h = relu(aggA@W1l + xr@W1r + b1), rounded
    agg_kernel<1, 1><<<(NN + 7) / 8, 256>>>(x, aggA);
    {
        dim3 grid(FHID / G_BN, (NN + G_BM - 1) / G_BM);
        gemm_tf32_kernel<<<grid, 256, G_SMEM_SZ>>>(
            aggA, Wt1l, FIN, xr, Wt1r, FIN, b1, nullptr, h, NN, FHID, 1, 1);
    }
    // Layer 2: p = h@W2l
    {
        dim3 grid(FOUT / G_BN, (NN + G_BM - 1) / G_BM);
        gemm_tf32_kernel<<<grid, 256, G_SMEM_SZ>>>(
            h, Wt2l, FHID, nullptr, nullptr, 0, nullptr, nullptr, p, NN, FOUT, 0, 0);
    }
    // agg2 = scatter_mean(p) (no rounding; residual only)
    agg_kernel<2, 0><<<(NN + 7) / 8, 256>>>(p, agg2);
    // out = h@W2r + b2 + agg2
    {
        dim3 grid(FOUT / G_BN, (NN + G_BM - 1) / G_BM);
        gemm_tf32_kernel<<<grid, 256, G_SMEM_SZ>>>(
            h, Wt2r, FHID, nullptr, nullptr, 0, b2, agg2, out, NN, FOUT, 0, 0);
    }
}

// round 8
// speedup vs baseline: 2.6920x; 1.2153x over previous
#include <cuda_runtime.h>
#include <cstdint>

// Problem constants (fixed by the dataset generator).
#define NN   40000
#define EE   640000
#define FIN  128
#define FHID 512
#define FOUT 256

#define SCAN_BLOCKS ((NN + 255) / 256)   // 157

// ---------------- scratch (static device globals; no allocation allowed) ----
__device__ int   g_is64;
__device__ int   g_cnt[NN];
__device__ int   g_bsum[256];            // >= SCAN_BLOCKS
__device__ int   g_rowptr[NN + 1];
__device__ int   g_cursor[NN];
__device__ int   g_col[EE];
__device__ float g_xr  [(size_t)NN * FIN];   // tf32-rounded copy of x   (20 MB)
__device__ float g_aggA[(size_t)NN * FIN];   // mean-aggregated x        (20 MB)
__device__ float g_h   [(size_t)NN * FHID];  // layer-1 output           (82 MB)
__device__ float g_p   [(size_t)NN * FOUT];  // h @ W2l                  (40 MB)
__device__ float g_q   [(size_t)NN * FOUT];  // h @ W2r + b2             (40 MB)
// transposed (and tf32-rounded) weights [N,K]
__device__ float g_Wt1l[FHID * FIN];
__device__ float g_Wt1r[FHID * FIN];
__device__ float g_Wt2lr[2 * FOUT * FHID];   // rows 0-255: W2l^T, 256-511: W2r^T

__device__ __forceinline__ float tf32r(float f) {
    uint32_t u;
    asm("cvt.rna.tf32.f32 %0, %1;" : "=r"(u) : "f"(f));
    return __uint_as_float(u);
}

// ---------------- edge dtype detection + direct readers -----------------------
__global__ void detect_kernel(const int* __restrict__ ei32) {
    if (threadIdx.x == 0 && blockIdx.x == 0) {
        int all0 = 1;
        for (int i = 0; i < 64; i++)
            if (ei32[2 * i + 1] != 0) all0 = 0;
        g_is64 = all0;
    }
}
__device__ __forceinline__ int edge_at(const int* __restrict__ ei, int is64, size_t idx) {
    return is64 ? (int)((const long long*)ei)[idx] : ei[idx];
}

// ---------------- CSR build --------------------------------------------------
__global__ void zero_cnt_kernel() {
    int i = blockIdx.x * blockDim.x + threadIdx.x;
    if (i < NN) g_cnt[i] = 0;
}
__global__ void hist_kernel(const int* __restrict__ ei) {
    int e = blockIdx.x * blockDim.x + threadIdx.x;
    if (e < EE) atomicAdd(&g_cnt[edge_at(ei, g_is64, (size_t)EE + e)], 1);
}

// 3-phase exclusive scan of g_cnt -> g_rowptr/g_cursor
__global__ void scan_phase1() {
    __shared__ int sh[256];
    int b = blockIdx.x, t = threadIdx.x;
    int i = b * 256 + t;
    int v = (i < NN) ? g_cnt[i] : 0;
    sh[t] = v;
    __syncthreads();
    for (int off = 128; off > 0; off >>= 1) {
        if (t < off) sh[t] += sh[t + off];
        __syncthreads();
    }
    if (t == 0) g_bsum[b] = sh[0];
}
__global__ void scan_phase2() {
    __shared__ int sh[256];
    int t = threadIdx.x;
    int v = (t < SCAN_BLOCKS) ? g_bsum[t] : 0;
    sh[t] = v;
    __syncthreads();
    for (int off = 1; off < 256; off <<= 1) {
        int u = (t >= off) ? sh[t - off] : 0;
        __syncthreads();
        sh[t] += u;
        __syncthreads();
    }
    g_bsum[t] = sh[t] - v;  // exclusive prefix of block sums
}
__global__ void scan_phase3() {
    __shared__ int sh[256];
    int b = blockIdx.x, t = threadIdx.x;
    int i = b * 256 + t;
    int v = (i < NN) ? g_cnt[i] : 0;
    sh[t] = v;
    __syncthreads();
    for (int off = 1; off < 256; off <<= 1) {
        int u = (t >= off) ? sh[t - off] : 0;
        __syncthreads();
        sh[t] += u;
        __syncthreads();
    }
    int excl = sh[t] - v + g_bsum[b];
    if (i < NN) {
        g_rowptr[i] = excl;
        g_cursor[i] = excl;
    }
    if (b == 0 && t == 0) g_rowptr[NN] = EE;
}

__global__ void fill_kernel(const int* __restrict__ ei) {
    int e = blockIdx.x * blockDim.x + threadIdx.x;
    if (e < EE) {
        int is64 = g_is64;
        int d = edge_at(ei, is64, (size_t)EE + e);
        int s = edge_at(ei, is64, (size_t)e);
        int pos = atomicAdd(&g_cursor[d], 1);
        g_col[pos] = s;
    }
}

// ---------------- weight transpose [K,N] -> [N,K] (+tf32 round) ---------------
// row_off lets layer-2 weights land concatenated in g_Wt2lr.
__global__ void transpose_kernel(const float* __restrict__ W,
                                 float* __restrict__ Wt, int K, int N, int row_off) {
    int idx = blockIdx.x * blockDim.x + threadIdx.x;
    if (idx < K * N) {
        int k = idx / N, n = idx % N;
        Wt[(size_t)(n + row_off) * K + k] = tf32r(W[idx]);
    }
}

// ---------------- round x into g_xr -------------------------------------------
__global__ void round_x_kernel(const float* __restrict__ x, float* __restrict__ xr) {
    int i = blockIdx.x * blockDim.x + threadIdx.x;
    const int TOT4 = NN * FIN / 4;
    if (i < TOT4) {
        float4 v = *(const float4*)(x + (size_t)i * 4);
        float4 o;
        o.x = tf32r(v.x); o.y = tf32r(v.y); o.z = tf32r(v.z); o.w = tf32r(v.w);
        *(float4*)(xr + (size_t)i * 4) = o;
    }
}

// ---------------- mean aggregation over CSR (unroll-4 for MLP) ----------------
// One warp per node; lane owns VPL float4 chunks.
// ROUND: tf32-round the mean. ADDQ: out = mean + qbase[node] (final residual).
template <int VPL, int ROUND, int ADDQ>
__global__ void agg_kernel(const float* __restrict__ feat,
                           const float* __restrict__ qbase,
                           float* __restrict__ out) {
    int node = blockIdx.x * (blockDim.x >> 5) + (threadIdx.x >> 5);
    if (node >= NN) return;
    int lane = threadIdx.x & 31;
    int beg = g_rowptr[node];
    int end = g_rowptr[node + 1];

    const int F = VPL * 128;
    float4 acc[VPL];
#pragma unroll
    for (int v = 0; v < VPL; v++) acc[v] = make_float4(0.f, 0.f, 0.f, 0.f);

    int j = beg;
    for (; j + 3 < end; j += 4) {
        int s0 = __ldg(&g_col[j]);
        int s1 = __ldg(&g_col[j + 1]);
        int s2 = __ldg(&g_col[j + 2]);
        int s3 = __ldg(&g_col[j + 3]);
        const float4* r0 = (const float4*)(feat + (size_t)s0 * F);
        const float4* r1 = (const float4*)(feat + (size_t)s1 * F);
        const float4* r2 = (const float4*)(feat + (size_t)s2 * F);
        const float4* r3 = (const float4*)(feat + (size_t)s3 * F);
#pragma unroll
        for (int v = 0; v < VPL; v++) {
            float4 a = r0[lane + v * 32];
            float4 b = r1[lane + v * 32];
            float4 c = r2[lane + v * 32];
            float4 d = r3[lane + v * 32];
            acc[v].x += (a.x + b.x) + (c.x + d.x);
            acc[v].y += (a.y + b.y) + (c.y + d.y);
            acc[v].z += (a.z + b.z) + (c.z + d.z);
            acc[v].w += (a.w + b.w) + (c.w + d.w);
        }
    }
    for (; j < end; j++) {
        int s0 = __ldg(&g_col[j]);
        const float4* r0 = (const float4*)(feat + (size_t)s0 * F);
#pragma unroll
        for (int v = 0; v < VPL; v++) {
            float4 a = r0[lane + v * 32];
            acc[v].x += a.x; acc[v].y += a.y; acc[v].z += a.z; acc[v].w += a.w;
        }
    }
    float inv = 1.0f / (float)max(end - beg, 1);
    float4* o = (float4*)(out + (size_t)node * F);
    const float4* qv = ADDQ ? (const float4*)(qbase + (size_t)node * F) : nullptr;
#pragma unroll
    for (int v = 0; v < VPL; v++) {
        acc[v].x *= inv; acc[v].y *= inv; acc[v].z *= inv; acc[v].w *= inv;
        if (ROUND) {
            acc[v].x = tf32r(acc[v].x); acc[v].y = tf32r(acc[v].y);
            acc[v].z = tf32r(acc[v].z); acc[v].w = tf32r(acc[v].w);
        }
        if (ADDQ) {
            float4 q = qv[lane + v * 32];
            acc[v].x += q.x; acc[v].y += q.y; acc[v].z += q.z; acc[v].w += q.w;
        }
        o[lane + v * 32] = acc[v];
    }
}

// ================= tf32 mma.sync GEMM (sm_80+ baseline ISA) ===================
// Operands PRE-ROUNDED to tf32 in gmem: mainloop feeds raw fp32 bits (no CVTs).
#define G_BM 128
#define G_BN 128
#define G_BK 32
#define G_PAD_STRIDE 36
#define G_STAGE_FLOATS (128 * G_PAD_STRIDE)
#define G_STAGE_BYTES (G_STAGE_FLOATS * 4)
#define G_SMEM_SZ (4 * G_STAGE_BYTES)

__device__ __forceinline__ uint32_t smem_u32(const void* p) {
    uint32_t a;
    asm("{ .reg .u64 t; cvta.to.shared.u64 t, %1; cvt.u32.u64 %0, t; }"
        : "=r"(a) : "l"(p));
    return a;
}
__device__ __forceinline__ void cp_async16(uint32_t dst, const void* src, int src_bytes) {
    asm volatile("cp.async.ca.shared.global [%0], [%1], 16, %2;"
                 :: "r"(dst), "l"(src), "r"(src_bytes) : "memory");
}
__device__ __forceinline__ void cp_commit() {
    asm volatile("cp.async.commit_group;" ::: "memory");
}
template <int NPEND>
__device__ __forceinline__ void cp_wait() {
    asm volatile("cp.async.wait_group %0;" :: "n"(NPEND) : "memory");
}
__device__ __forceinline__ void mma_tf32(float* d, const uint32_t* a, const uint32_t* b) {
    asm volatile(
        "mma.sync.aligned.m16n8k8.row.col.f32.tf32.tf32.f32 "
        "{%0,%1,%2,%3}, {%4,%5,%6,%7}, {%8,%9}, {%0,%1,%2,%3};"
        : "+f"(d[0]), "+f"(d[1]), "+f"(d[2]), "+f"(d[3])
        : "r"(a[0]), "r"(a[1]), "r"(a[2]), "r"(a[3]), "r"(b[0]), "r"(b[1]));
}

__device__ __forceinline__ void gemm_issue_tile(
    const float* __restrict__ src, int row0, int row_lim, int K, int k0,
    uint32_t dst_base, int tid) {
#pragma unroll
    for (int u = 0; u < 4; u++) {
        int id  = u * 256 + tid;
        int row = id >> 3;
        int c   = id & 7;
        int gr  = row0 + row;
        int ok  = gr < row_lim;
        const float* s = src + (size_t)(ok ? gr : (row_lim - 1)) * K + k0 + c * 4;
        cp_async16(dst_base + row * (G_PAD_STRIDE * 4) + c * 16, s, ok ? 16 : 0);
    }
}

// split_n == 0: C[M,N] with optional bias/Dres/relu/round.
// split_n  > 0: cols < split_n -> C   (no bias),
//               cols >= split_n -> C2 (+bias[n-split_n]); both [M, split_n].
__global__ void __launch_bounds__(256)
gemm_tf32_kernel(const float* __restrict__ A1, const float* __restrict__ B1t, int K1,
                 const float* __restrict__ A2, const float* __restrict__ B2t, int K2,
                 const float* __restrict__ bias, const float* __restrict__ Dres,
                 float* __restrict__ C, float* __restrict__ C2,
                 int M, int N, int relu, int round_out, int split_n) {
    extern __shared__ float smem[];
    uint32_t sb = smem_u32(smem);

    int tid  = threadIdx.x;
    int lane = tid & 31;
    int wid  = tid >> 5;
    int wm   = wid & 3;
    int wn   = wid >> 2;
    int m0 = blockIdx.y * G_BM;
    int n0 = blockIdx.x * G_BN;

    const int kt1 = K1 >> 5;
    const int KT  = kt1 + (K2 >> 5);

    float acc[2][8][4];
#pragma unroll
    for (int i = 0; i < 2; i++)
#pragma unroll
        for (int j = 0; j < 8; j++)
#pragma unroll
            for (int q = 0; q < 4; q++) acc[i][j][q] = 0.f;

    auto issue = [&](int kt) {
        const float* A;
        const float* B;
        int K, kk;
        if (kt < kt1) { A = A1; B = B1t; K = K1; kk = kt; }
        else          { A = A2; B = B2t; K = K2; kk = kt - kt1; }
        int s = kt & 1;
        uint32_t aB = sb + (uint32_t)(s * 2 * G_STAGE_BYTES);
        uint32_t bB = aB + G_STAGE_BYTES;
        gemm_issue_tile(A, m0, M, K, kk * G_BK, aB, tid);
        gemm_issue_tile(B, n0, N, K, kk * G_BK, bB, tid);
    };

    issue(0);
    cp_commit();

    int r_lo = (lane >> 2);
    int k_lo = (lane & 3);

    for (int kt = 0; kt < KT; kt++) {
        if (kt + 1 < KT) {
            issue(kt + 1);
            cp_commit();
            cp_wait<1>();
        } else {
            cp_wait<0>();
        }
        __syncthreads();

        int s = kt & 1;
        const uint32_t* As = (const uint32_t*)(smem + (size_t)s * 2 * G_STAGE_FLOATS);
        const uint32_t* Bs = As + G_STAGE_FLOATS;

#pragma unroll
        for (int ks = 0; ks < 4; ks++) {
            int k = ks * 8 + k_lo;
            uint32_t af[2][4];
#pragma unroll
            for (int tm = 0; tm < 2; tm++) {
                int r = wm * 32 + tm * 16 + r_lo;
                af[tm][0] = As[r * G_PAD_STRIDE + k];
                af[tm][1] = As[(r + 8) * G_PAD_STRIDE + k];
                af[tm][2] = As[r * G_PAD_STRIDE + k + 4];
                af[tm][3] = As[(r + 8) * G_PAD_STRIDE + k + 4];
            }
            uint32_t bf[8][2];
#pragma unroll
            for (int tn = 0; tn < 8; tn++) {
                int n = wn * 64 + tn * 8 + r_lo;
                bf[tn][0] = Bs[n * G_PAD_STRIDE + k];
                bf[tn][1] = Bs[n * G_PAD_STRIDE + k + 4];
            }
#pragma unroll
            for (int tm = 0; tm < 2; tm++)
#pragma unroll
                for (int tn = 0; tn < 8; tn++)
                    mma_tf32(acc[tm][tn], af[tm], bf[tn]);
        }
        __syncthreads();
    }

    // epilogue
#pragma unroll
    for (int tm = 0; tm < 2; tm++) {
#pragma unroll
        for (int half = 0; half < 2; half++) {
            int m = m0 + wm * 32 + tm * 16 + half * 8 + r_lo;
            if (m >= M) continue;
#pragma unroll
            for (int tn = 0; tn < 8; tn++) {
                int n = n0 + wn * 64 + tn * 8 + k_lo * 2;
                float2 o;
                o.x = acc[tm][tn][half * 2 + 0];
                o.y = acc[tm][tn][half * 2 + 1];
                if (split_n) {
                    if (n < split_n) {
                        *(float2*)(C + (size_t)m * split_n + n) = o;
                    } else {
                        int n2 = n - split_n;
                        float2 bv = *(const float2*)(bias + n2);
                        o.x += bv.x; o.y += bv.y;
                        *(float2*)(C2 + (size_t)m * split_n + n2) = o;
                    }
                    continue;
                }
                if (bias) {
                    float2 bv = *(const float2*)(bias + n);
                    o.x += bv.x; o.y += bv.y;
                }
                if (Dres) {
                    float2 dv = *(const float2*)(Dres + (size_t)m * N + n);
                    o.x += dv.x; o.y += dv.y;
                }
                if (relu) {
                    o.x = fmaxf(o.x, 0.f);
                    o.y = fmaxf(o.y, 0.f);
                }
                if (round_out) {
                    o.x = tf32r(o.x);
                    o.y = tf32r(o.y);
                }
                *(float2*)(C + (size_t)m * N + n) = o;
            }
        }
    }
}

// ---------------- launcher -----------------------------------------------------
extern "C" void kernel_launch(void* const* d_in, const int* in_sizes, int n_in,
                              void* d_out, int out_size) {
    const float* x   = (const float*)d_in[0];
    const int*   ei  = (const int*)d_in[1];   // int32 OR int64 (device-detected)
    const float* W1l = (const float*)d_in[2];
    const float* b1  = (const float*)d_in[3];
    const float* W1r = (const float*)d_in[4];
    const float* W2l = (const float*)d_in[5];
    const float* b2  = (const float*)d_in[6];
    const float* W2r = (const float*)d_in[7];
    float* out = (float*)d_out;

    float *xr, *aggA, *h, *p, *q, *Wt1l, *Wt1r, *Wt2lr;
    cudaGetSymbolAddress((void**)&xr,    g_xr);
    cudaGetSymbolAddress((void**)&aggA,  g_aggA);
    cudaGetSymbolAddress((void**)&h,     g_h);
    cudaGetSymbolAddress((void**)&p,     g_p);
    cudaGetSymbolAddress((void**)&q,     g_q);
    cudaGetSymbolAddress((void**)&Wt1l,  g_Wt1l);
    cudaGetSymbolAddress((void**)&Wt1r,  g_Wt1r);
    cudaGetSymbolAddress((void**)&Wt2lr, g_Wt2lr);

    static int smem_set = 0;
    if (!smem_set) {
        cudaFuncSetAttribute(gemm_tf32_kernel,
                             cudaFuncAttributeMaxDynamicSharedMemorySize, G_SMEM_SZ);
        smem_set = 1;
    }

    // Edge dtype detection, CSR build (multi-block scan)
    detect_kernel<<<1, 32>>>(ei);
    zero_cnt_kernel<<<(NN + 255) / 256, 256>>>();
    hist_kernel<<<(EE + 255) / 256, 256>>>(ei);
    scan_phase1<<<SCAN_BLOCKS, 256>>>();
    scan_phase2<<<1, 256>>>();
    scan_phase3<<<SCAN_BLOCKS, 256>>>();
    fill_kernel<<<(EE + 255) / 256, 256>>>(ei);

    // Pre-rounded operands
    round_x_kernel<<<(NN * FIN / 4 + 255) / 256, 256>>>(x, xr);
    transpose_kernel<<<(FIN * FHID + 255) / 256, 256>>>(W1l, Wt1l, FIN, FHID, 0);
    transpose_kernel<<<(FIN * FHID + 255) / 256, 256>>>(W1r, Wt1r, FIN, FHID, 0);
    transpose_kernel<<<(FHID * FOUT + 255) / 256, 256>>>(W2l, Wt2lr, FHID, FOUT, 0);
    transpose_kernel<<<(FHID * FOUT + 255) / 256, 256>>>(W2r, Wt2lr, FHID, FOUT, FOUT);

    // Layer 1: aggregate x (rounded mean), h = relu(aggA@W1l + xr@W1r + b1), rounded
    agg_kernel<1, 1, 0><<<(NN + 7) / 8, 256>>>(x, nullptr, aggA);
    {
        dim3 grid(FHID / G_BN, (NN + G_BM - 1) / G_BM);
        gemm_tf32_kernel<<<grid, 256, G_SMEM_SZ>>>(
            aggA, Wt1l, FIN, xr, Wt1r, FIN, b1, nullptr, h, nullptr,
            NN, FHID, 1, 1, 0);
    }
    // Layer 2 fused GEMM: cols 0-255 -> p = h@W2l, cols 256-511 -> q = h@W2r + b2
    {
        dim3 grid((2 * FOUT) / G_BN, (NN + G_BM - 1) / G_BM);
        gemm_tf32_kernel<<<grid, 256, G_SMEM_SZ>>>(
            h, Wt2lr, FHID, nullptr, nullptr, 0, b2, nullptr, p, q,
            NN, 2 * FOUT, 0, 0, FOUT);
    }
    // out = scatter_mean(p) + q   (residual folded into agg epilogue)
    agg_kernel<2, 0, 1><<<(NN + 7) / 8, 256>>>(p, q, out);
}